// round 10
// baseline (speedup 1.0000x reference)
#include <cuda_runtime.h>

#define NN 100000
#define EE 3200000
#define FIN 128
#define HID 16
#define NCLS 40
#define NB_SCAN 98            // ceil(NN/1024)

// Scratch (device globals)
__device__ int    g_cnt[NN];        // in-degree (without self loop)
__device__ int    g_fill[NN];
__device__ int    g_off[NN];        // exclusive prefix of cnt
__device__ int    g_blk[128];
__device__ int    g_blkpre[128];
__device__ int    g_ssrc[EE];       // src ids sorted by dst
__device__ float  g_dinv[NN];
__device__ float4 g_hs1[NN * 4];    // (x@W1) * dinv[n], [N][16]
__device__ float4 g_hs2[NN * 4];    // relu(layer1)*dinv[n]

__device__ __forceinline__ int warp_incl_scan(int v, int lane) {
#pragma unroll
    for (int off = 1; off < 32; off <<= 1) {
        int n = __shfl_up_sync(0xffffffffu, v, off);
        if (lane >= off) v += n;
    }
    return v;
}

// K1: zero counters
__global__ void k_zero() {
    int i = blockIdx.x * blockDim.x + threadIdx.x;
    if (i < NN) { g_cnt[i] = 0; g_fill[i] = 0; }
}

// K2: histogram of dst
__global__ void k_hist(const int* __restrict__ ei) {
    int e = blockIdx.x * blockDim.x + threadIdx.x;
    if (e < EE) atomicAdd(&g_cnt[ei[EE + e]], 1);
}

// K3: per-1024-block totals
__global__ void k_s1() {
    __shared__ int wsum[8];
    int t = threadIdx.x, lane = t & 31, wid = t >> 5;
    int i0 = blockIdx.x * 1024 + t * 4;
    int ts = 0;
    if (i0 + 3 < NN) {
        int4 c = *(const int4*)&g_cnt[i0];
        ts = c.x + c.y + c.z + c.w;
    } else {
        for (int k = 0; k < 4; k++) if (i0 + k < NN) ts += g_cnt[i0 + k];
    }
#pragma unroll
    for (int off = 16; off > 0; off >>= 1) ts += __shfl_xor_sync(0xffffffffu, ts, off);
    if (lane == 0) wsum[wid] = ts;
    __syncthreads();
    if (t == 0) {
        int s = 0;
#pragma unroll
        for (int w = 0; w < 8; w++) s += wsum[w];
        g_blk[blockIdx.x] = s;
    }
}

// K4: exclusive scan of block totals (single block, 128 threads)
// Second-level scan executed by ALL 32 lanes of warp 0 (no divergent shfl).
__global__ void k_s2() {
    __shared__ int wpre[4];
    int t = threadIdx.x, lane = t & 31, wid = t >> 5;
    int v = (t < NB_SCAN) ? g_blk[t] : 0;
    int incl = warp_incl_scan(v, lane);
    if (lane == 31) wpre[wid] = incl;
    __syncthreads();
    if (wid == 0) {
        int wv = (lane < 4) ? wpre[lane] : 0;
        int wi = warp_incl_scan(wv, lane);
        if (lane < 4) wpre[lane] = wi - wv;
    }
    __syncthreads();
    if (t < NB_SCAN) g_blkpre[t] = wpre[wid] + incl - v;
}

// K5: write per-item exclusive offsets + dinv
__global__ void k_s3() {
    __shared__ int wsum[8];
    __shared__ int wpre[8];
    int t = threadIdx.x, lane = t & 31, wid = t >> 5;
    int i0 = blockIdx.x * 1024 + t * 4;
    int v0 = 0, v1 = 0, v2 = 0, v3 = 0;
    if (i0 + 3 < NN) {
        int4 c = *(const int4*)&g_cnt[i0];
        v0 = c.x; v1 = c.y; v2 = c.z; v3 = c.w;
    } else {
        if (i0 + 0 < NN) v0 = g_cnt[i0 + 0];
        if (i0 + 1 < NN) v1 = g_cnt[i0 + 1];
        if (i0 + 2 < NN) v2 = g_cnt[i0 + 2];
        if (i0 + 3 < NN) v3 = g_cnt[i0 + 3];
    }
    int ts = v0 + v1 + v2 + v3;
    int incl = warp_incl_scan(ts, lane);
    if (lane == 31) wsum[wid] = incl;
    __syncthreads();
    if (wid == 0) {
        int wv = (lane < 8) ? wsum[lane] : 0;
        int wi = warp_incl_scan(wv, lane);
        if (lane < 8) wpre[lane] = wi - wv;
    }
    __syncthreads();
    int base = g_blkpre[blockIdx.x] + wpre[wid] + incl - ts;
    if (i0 + 0 < NN) { g_off[i0 + 0] = base;                g_dinv[i0 + 0] = rsqrtf((float)(v0 + 1)); }
    if (i0 + 1 < NN) { g_off[i0 + 1] = base + v0;           g_dinv[i0 + 1] = rsqrtf((float)(v1 + 1)); }
    if (i0 + 2 < NN) { g_off[i0 + 2] = base + v0 + v1;      g_dinv[i0 + 2] = rsqrtf((float)(v2 + 1)); }
    if (i0 + 3 < NN) { g_off[i0 + 3] = base + v0 + v1 + v2; g_dinv[i0 + 3] = rsqrtf((float)(v3 + 1)); }
}

// K6: place edges sorted by destination
__global__ void k_place(const int* __restrict__ ei) {
    int e = blockIdx.x * blockDim.x + threadIdx.x;
    if (e >= EE) return;
    int s = ei[e];
    int d = ei[EE + e];
    int p = g_off[d] + atomicAdd(&g_fill[d], 1);
    g_ssrc[p] = s;
}

// K7: hs1 = (x @ W1) * dinv — smem-tiled; q taken from top bits so every
// sW read is warp-uniform (broadcast, no smem port pressure).
__global__ __launch_bounds__(256) void k_xw1(const float* __restrict__ x,
                                             const float* __restrict__ W1) {
    __shared__ float4 sx[64 * 33];     // padded row stride 33 float4
    __shared__ float4 sW[512];         // W1 [128][16] as float4
    int t = threadIdx.x;
    int n0 = blockIdx.x * 64;

    for (int i = t; i < 512; i += 256) sW[i] = ((const float4*)W1)[i];
#pragma unroll
    for (int r = 0; r < 8; r++) {
        int idx = t + 256 * r;          // 0..2047
        int row = idx >> 5, col = idx & 31;
        int n = n0 + row;
        float4 v = make_float4(0.f, 0.f, 0.f, 0.f);
        if (n < NN) v = ((const float4*)x)[n * 32 + col];
        sx[row * 33 + col] = v;
    }
    __syncthreads();

    int q = t >> 6;          // warp-uniform output quad
    int node = t & 63;
    int n = n0 + node;
    float4 acc = make_float4(0.f, 0.f, 0.f, 0.f);
#pragma unroll
    for (int k4 = 0; k4 < 32; k4++) {
        float4 xv = sx[node * 33 + k4];
#pragma unroll
        for (int c = 0; c < 4; c++) {
            float a = (c == 0) ? xv.x : (c == 1) ? xv.y : (c == 2) ? xv.z : xv.w;
            float4 w = sW[(k4 * 4 + c) * 4 + q];
            acc.x += a * w.x; acc.y += a * w.y; acc.z += a * w.z; acc.w += a * w.w;
        }
    }
    if (n < NN) {
        float dv = g_dinv[n];
        g_hs1[n * 4 + q] = make_float4(acc.x * dv, acc.y * dv, acc.z * dv, acc.w * dv);
    }
}

// Warp-cooperative CSR gather body: coalesced ssrc preload + shfl distribute,
// 4 independent hs loads in flight per lane.
__device__ __forceinline__ float4 gather_rows(const float4* __restrict__ hs,
                                              int base, int deg, int lane) {
    int q = lane & 3, g = lane >> 2;
    float4 acc = make_float4(0.f, 0.f, 0.f, 0.f);
    for (int k0 = 0; k0 < deg; k0 += 32) {
        int idx = k0 + lane;
        int sv = (idx < deg) ? g_ssrc[base + idx] : 0;
#pragma unroll
        for (int it = 0; it < 4; it++) {
            int j = g + 8 * it;
            int s = __shfl_sync(0xffffffffu, sv, j);
            if (k0 + j < deg) {
                float4 v = hs[s * 4 + q];
                acc.x += v.x; acc.y += v.y; acc.z += v.z; acc.w += v.w;
            }
        }
    }
#pragma unroll
    for (int off = 16; off >= 4; off >>= 1) {
        acc.x += __shfl_xor_sync(0xffffffffu, acc.x, off);
        acc.y += __shfl_xor_sync(0xffffffffu, acc.y, off);
        acc.z += __shfl_xor_sync(0xffffffffu, acc.z, off);
        acc.w += __shfl_xor_sync(0xffffffffu, acc.w, off);
    }
    return acc;
}

// K8: layer-1 gather + bias + relu; writes hs2 = relu(agg1)*dinv
__global__ __launch_bounds__(256) void k_gather1(const float* __restrict__ b1) {
    int warp = (blockIdx.x * blockDim.x + threadIdx.x) >> 5;
    if (warp >= NN) return;
    int lane = threadIdx.x & 31;
    int q = lane & 3;
    int d = warp;
    float4 acc = gather_rows(g_hs1, g_off[d], g_cnt[d], lane);
    float4 self = g_hs1[d * 4 + q];
    float dv = g_dinv[d];
    float4 bq = ((const float4*)b1)[q];
    float4 h;
    h.x = fmaxf(dv * (acc.x + self.x) + bq.x, 0.f) * dv;
    h.y = fmaxf(dv * (acc.y + self.y) + bq.y, 0.f) * dv;
    h.z = fmaxf(dv * (acc.z + self.z) + bq.z, 0.f) * dv;
    h.w = fmaxf(dv * (acc.w + self.w) + bq.w, 0.f) * dv;
    if (lane < 4) g_hs2[d * 4 + q] = h;
}

// K9: layer-2 gather + W2 GEMM + log_softmax, fused
__global__ __launch_bounds__(256) void k_gather2(const float* __restrict__ W2,
                                                 const float* __restrict__ b2,
                                                 float* __restrict__ out) {
    __shared__ float sW2[HID * NCLS];
    __shared__ float sB2[NCLS];
    for (int i = threadIdx.x; i < HID * NCLS; i += blockDim.x) sW2[i] = W2[i];
    for (int i = threadIdx.x; i < NCLS; i += blockDim.x) sB2[i] = b2[i];
    __syncthreads();

    int warp = (blockIdx.x * blockDim.x + threadIdx.x) >> 5;
    if (warp >= NN) return;
    int lane = threadIdx.x & 31;
    int q = lane & 3;
    int d = warp;
    float4 acc = gather_rows(g_hs2, g_off[d], g_cnt[d], lane);
    float4 self = g_hs2[d * 4 + q];
    float dv = g_dinv[d];
    float4 agg;
    agg.x = dv * (acc.x + self.x);
    agg.y = dv * (acc.y + self.y);
    agg.z = dv * (acc.z + self.z);
    agg.w = dv * (acc.w + self.w);

    // broadcast all 16 agg values to every lane
    float a[HID];
#pragma unroll
    for (int k = 0; k < HID; k++) {
        int comp = k & 3;
        float send = (comp == 0) ? agg.x : (comp == 1) ? agg.y : (comp == 2) ? agg.z : agg.w;
        a[k] = __shfl_sync(0xffffffffu, send, k >> 2);
    }

    int j = lane;                 // class j and (j<8) class 32+j
    int j2 = 32 + (j & 7);
    float z1 = sB2[j];
    float z2 = sB2[j2];
#pragma unroll
    for (int k = 0; k < HID; k++) {
        z1 += a[k] * sW2[k * NCLS + j];
        z2 += a[k] * sW2[k * NCLS + j2];
    }
    bool has2 = (j < 8);

    float lm = has2 ? fmaxf(z1, z2) : z1;
#pragma unroll
    for (int off = 16; off > 0; off >>= 1)
        lm = fmaxf(lm, __shfl_xor_sync(0xffffffffu, lm, off));
    float ls = __expf(z1 - lm) + (has2 ? __expf(z2 - lm) : 0.f);
#pragma unroll
    for (int off = 16; off > 0; off >>= 1)
        ls += __shfl_xor_sync(0xffffffffu, ls, off);
    float l = lm + __logf(ls);

    out[d * NCLS + j] = z1 - l;
    if (has2) out[d * NCLS + j2] = z2 - l;
}

extern "C" void kernel_launch(void* const* d_in, const int* in_sizes, int n_in,
                              void* d_out, int out_size) {
    const float* x  = nullptr;
    const int*   ei = nullptr;
    const float* W1 = nullptr;
    const float* b1 = nullptr;
    const float* W2 = nullptr;
    const float* b2 = nullptr;
    for (int i = 0; i < n_in; i++) {
        switch (in_sizes[i]) {
            case NN * FIN:    x  = (const float*)d_in[i]; break;
            case 2 * EE:      ei = (const int*)d_in[i];   break;
            case FIN * HID:   W1 = (const float*)d_in[i]; break;
            case HID:         b1 = (const float*)d_in[i]; break;
            case HID * NCLS:  W2 = (const float*)d_in[i]; break;
            case NCLS:        b2 = (const float*)d_in[i]; break;
            default: break;
        }
    }
    float* out = (float*)d_out;

    k_zero<<<(NN + 255) / 256, 256>>>();
    k_hist<<<(EE + 511) / 512, 512>>>(ei);
    k_s1<<<NB_SCAN, 256>>>();
    k_s2<<<1, 128>>>();
    k_s3<<<NB_SCAN, 256>>>();
    k_place<<<(EE + 511) / 512, 512>>>(ei);
    k_xw1<<<(NN + 63) / 64, 256>>>(x, W1);
    k_gather1<<<(NN * 32 + 255) / 256, 256>>>(b1);
    k_gather2<<<(NN * 32 + 255) / 256, 256>>>(W2, b2, out);
}